// round 6
// baseline (speedup 1.0000x reference)
#include <cuda_runtime.h>
#include <cuda_bf16.h>
#include <cstdint>

// Problem constants
#define NN   4096
#define DD   128
#define HH   8
#define ALPHA 0.2f
#define LN_EPS 1e-5f
#define NCH  128           // 128 chunks of 32 j

typedef unsigned long long u64;

// ---------------- scratch (device globals; no allocation allowed) ----------------
// Wh^T in m16n8k16 A-fragment order, split hi/lo bf16:
// elem index = ((((h*NCH + ch)*2 + s)*8 + dt)*32 + lane)*8 + reg*2 + half
__device__ __nv_bfloat16 g_whAhi[(size_t)HH * NCH * 2 * 8 * 32 * 8];  // 8 MB
__device__ __nv_bfloat16 g_whAlo[(size_t)HH * NCH * 2 * 8 * 32 * 8];  // 8 MB
__device__ float4   g_fq [HH * NN];                 // (f1, e^f1, e^{a f1}, 0)
__device__ float4   g_fk [HH * NN];                 // (f2, e^f2, e^{a f2}, 0)
__device__ float    g_cat[(size_t)NN * (HH * DD)];  // [n][h*128+d], 16 MB
__device__ unsigned g_adjbits[NN * (NN / 32)];      // bit-packed adj, 2 MB

// ---------------- helpers ----------------
__device__ __forceinline__ u64 pack2(float x, float y) {
    u64 r; asm("mov.b64 %0, {%1, %2};" : "=l"(r) : "f"(x), "f"(y)); return r;
}
__device__ __forceinline__ float2 unpack2(u64 v) {
    float2 r; asm("mov.b64 {%0, %1}, %2;" : "=f"(r.x), "=f"(r.y) : "l"(v)); return r;
}
__device__ __forceinline__ u64 ffma2(u64 a, u64 b, u64 c) {
    u64 d; asm("fma.rn.f32x2 %0, %1, %2, %3;" : "=l"(d) : "l"(a), "l"(b), "l"(c)); return d;
}
__device__ __forceinline__ float elu1(float x) { return x > 0.f ? x : expm1f(x); }
__device__ __forceinline__ uint32_t bf2_bits(__nv_bfloat162 v) {
    return *reinterpret_cast<uint32_t*>(&v);
}

// m16n8k16 bf16 mma: D(f32) += A(bf16,row) * B(bf16,col)
__device__ __forceinline__ void mma_bf16(float c[4], uint4 a, uint2 b) {
    asm volatile(
        "mma.sync.aligned.m16n8k16.row.col.f32.bf16.bf16.f32 "
        "{%0,%1,%2,%3}, {%4,%5,%6,%7}, {%8,%9}, {%0,%1,%2,%3};"
        : "+f"(c[0]), "+f"(c[1]), "+f"(c[2]), "+f"(c[3])
        : "r"(a.x), "r"(a.y), "r"(a.z), "r"(a.w), "r"(b.x), "r"(b.y));
}

// =================================================================
// Kernel 0: bit-pack adjacency. One warp per 32 columns.
// =================================================================
__global__ void pack_kernel(const int* __restrict__ adj) {
    int w    = blockIdx.x * 8 + (threadIdx.x >> 5);
    int lane = threadIdx.x & 31;
    int av = adj[(size_t)w * 32 + lane];
    unsigned m = __ballot_sync(0xffffffffu, av > 0);
    if (lane == 0) g_adjbits[w] = m;
}

// =================================================================
// Kernel 1: Wh = nodes @ W[h]; writes
//   - g_whAhi/g_whAlo : bf16 hi/lo A-fragments for the attention MMA
//   - g_fq/g_fk : f1/f2 + exp factors
// grid (64, 8), block 256. 64-node tile per CTA.
// =================================================================
__global__ void wh_kernel(const float* __restrict__ nodes, const float* __restrict__ W,
                          const float* __restrict__ a1, const float* __restrict__ a2) {
    __shared__ float ns[64][DD];
    const int h  = blockIdx.y;
    const int nb = blockIdx.x * 64;
    const int tid = threadIdx.x;

#pragma unroll
    for (int i = 0; i < 8; i++) {
        int f  = tid + 256 * i;
        int r  = f >> 5, c4 = f & 31;
        *(float4*)&ns[r][c4 * 4] = *(const float4*)&nodes[(size_t)(nb + r) * DD + c4 * 4];
    }
    __syncthreads();

    const int dg = tid & 31;   // lane: dims dg*4 .. dg*4+3
    const int ng = tid >> 5;   // warp: nodes ng*8 .. ng*8+7
    const float* Wb = W + (size_t)h * DD * DD;

    u64 acc[8][2];
#pragma unroll
    for (int n = 0; n < 8; n++) { acc[n][0] = 0ULL; acc[n][1] = 0ULL; }

#pragma unroll 4
    for (int k = 0; k < DD; k++) {
        float4 w4 = __ldg((const float4*)&Wb[k * DD + dg * 4]);
        u64 wxy = pack2(w4.x, w4.y);
        u64 wzw = pack2(w4.z, w4.w);
#pragma unroll
        for (int n = 0; n < 8; n++) {
            float s = ns[ng * 8 + n][k];
            u64 ss = pack2(s, s);
            acc[n][0] = ffma2(ss, wxy, acc[n][0]);
            acc[n][1] = ffma2(ss, wzw, acc[n][1]);
        }
    }

    float4 wh4[8];
#pragma unroll
    for (int n = 0; n < 8; n++) {
        float2 a = unpack2(acc[n][0]);
        float2 b = unpack2(acc[n][1]);
        wh4[n] = make_float4(a.x, a.y, b.x, b.y);
    }

    // ---- f1/f2 + exp factors ----
    float4 A1 = __ldg((const float4*)&a1[h * DD + dg * 4]);
    float4 A2 = __ldg((const float4*)&a2[h * DD + dg * 4]);
    float s1[8], s2[8];
#pragma unroll
    for (int n = 0; n < 8; n++) {
        s1[n] = wh4[n].x * A1.x + wh4[n].y * A1.y + wh4[n].z * A1.z + wh4[n].w * A1.w;
        s2[n] = wh4[n].x * A2.x + wh4[n].y * A2.y + wh4[n].z * A2.z + wh4[n].w * A2.w;
    }
#pragma unroll
    for (int o = 16; o > 0; o >>= 1) {
#pragma unroll
        for (int n = 0; n < 8; n++) {
            s1[n] += __shfl_xor_sync(0xffffffffu, s1[n], o);
            s2[n] += __shfl_xor_sync(0xffffffffu, s2[n], o);
        }
    }
    if (dg < 8) {
        float v1 = s1[0], v2 = s2[0];
#pragma unroll
        for (int n = 1; n < 8; n++)
            if (dg == n) { v1 = s1[n]; v2 = s2[n]; }
        int node = nb + ng * 8 + dg;
        g_fq[h * NN + node] = make_float4(v1, expf(v1), expf(ALPHA * v1), 0.f);
        g_fk[h * NN + node] = make_float4(v2, expf(v2), expf(ALPHA * v2), 0.f);
    }

    // ---- bf16 hi/lo A-fragment write ----
#pragma unroll
    for (int n = 0; n < 8; n++) {
        int j  = nb + ng * 8 + n;
        int ch = j >> 5, s = (j >> 4) & 1, jl = j & 15;
        int jlane = (jl & 7) >> 1;
        int jrhi  = (jl >> 3) & 1;
        int half  = jl & 1;
        size_t cb = (((size_t)h * NCH + ch) * 2 + s) * 8;
        float vals[4] = {wh4[n].x, wh4[n].y, wh4[n].z, wh4[n].w};
#pragma unroll
        for (int q = 0; q < 4; q++) {
            int d = dg * 4 + q;
            int dt = d >> 4, row = d & 15;
            int lane2 = (row & 7) * 4 + jlane;
            int reg   = (row >> 3) | (jrhi << 1);
            size_t ei = ((cb + dt) * 32 + lane2) * 8 + reg * 2 + half;
            float v = vals[q];
            __nv_bfloat16 hv = __float2bfloat16(v);
            g_whAhi[ei] = hv;
            g_whAlo[ei] = __float2bfloat16(v - __bfloat162float(hv));
        }
    }
}

// =================================================================
// Kernel 2: attention via 3-pass bf16 hi/lo mma.sync (m16n8k16).
// grid (32, 8): 128-query tile per CTA for head h. block 256.
// Consumer: warp wid owns d-tile [wid*16, +16) x all 128 q.
// Producer: warp wid makes B-frags for (s = wid>>2, nt in (wid&3)*4..+4).
// =================================================================
__global__ void __launch_bounds__(256, 2) attn_kernel() {
    __shared__ uint2 pbh[2][2][16][32];     // 16 KB : hi B-frags [buf][s][nt][lane]
    __shared__ uint2 pbl[2][2][16][32];     // 16 KB : lo B-frags
    __shared__ float4 fqs[128];             //  2 KB
    __shared__ float  lsum[128];

    const int h     = blockIdx.y;
    const int qbase = blockIdx.x * 128;
    const int tid   = threadIdx.x;
    const int wid   = tid >> 5;
    const int lane  = tid & 31;
    const int r4 = lane >> 2;
    const int c4 = lane & 3;
    const int sown = wid >> 2;      // producer k-step (0/1)
    const int ntg  = wid & 3;       // producer nt group (x4)

    if (tid < 128) {
        fqs[tid]  = g_fq[h * NN + qbase + tid];
        lsum[tid] = 0.f;
    }
    __syncthreads();

    float acc[16][4];
#pragma unroll
    for (int nt = 0; nt < 16; nt++)
#pragma unroll
        for (int i = 0; i < 4; i++) acc[nt][i] = 0.f;
    float lpart[4] = {0.f, 0.f, 0.f, 0.f};

    const float4*   fkb = g_fk + h * NN;
    const unsigned* ab  = g_adjbits + (size_t)qbase * (NN / 32);
    const uint4* Ahi = (const uint4*)g_whAhi;
    const uint4* Alo = (const uint4*)g_whAlo;

    float4 fk0, fk1, fk2, fk3;
    unsigned mw0, mw1, mw2, mw3;
    const int shv = sown * 16 + 2 * c4;

    // issue producer loads for chunk ch
#define LOADP(CH) do {                                                           \
    int _jb = (CH) * 32 + sown * 16 + 2 * c4;                                    \
    fk0 = __ldg(&fkb[_jb]);     fk1 = __ldg(&fkb[_jb + 1]);                      \
    fk2 = __ldg(&fkb[_jb + 8]); fk3 = __ldg(&fkb[_jb + 9]);                      \
    mw0 = __ldg(&ab[(size_t)((ntg * 4 + 0) * 8 + r4) * (NN / 32) + (CH)]);       \
    mw1 = __ldg(&ab[(size_t)((ntg * 4 + 1) * 8 + r4) * (NN / 32) + (CH)]);       \
    mw2 = __ldg(&ab[(size_t)((ntg * 4 + 2) * 8 + r4) * (NN / 32) + (CH)]);       \
    mw3 = __ldg(&ab[(size_t)((ntg * 4 + 3) * 8 + r4) * (NN / 32) + (CH)]);       \
} while (0)

    // compute P + split + store B-frags into buffer BUF (uses loaded fk/mw)
#define CALCP(BUF) do {                                                          \
    unsigned mws[4] = {mw0, mw1, mw2, mw3};                                      \
    _Pragma("unroll")                                                            \
    for (int i = 0; i < 4; i++) {                                                \
        int nt = ntg * 4 + i;                                                    \
        float4 fq = fqs[nt * 8 + r4];                                            \
        unsigned mw = mws[i];                                                    \
        float t0 = fq.x + fk0.x;                                                 \
        float p0 = (t0 >= 0.f) ? fq.y * fk0.y : fq.z * fk0.z;                    \
        p0 = ((mw >> shv) & 1u) ? p0 : 0.f;                                      \
        float t1 = fq.x + fk1.x;                                                 \
        float p1 = (t1 >= 0.f) ? fq.y * fk1.y : fq.z * fk1.z;                    \
        p1 = ((mw >> (shv + 1)) & 1u) ? p1 : 0.f;                                \
        float t2 = fq.x + fk2.x;                                                 \
        float p2 = (t2 >= 0.f) ? fq.y * fk2.y : fq.z * fk2.z;                    \
        p2 = ((mw >> (shv + 8)) & 1u) ? p2 : 0.f;                                \
        float t3 = fq.x + fk3.x;                                                 \
        float p3 = (t3 >= 0.f) ? fq.y * fk3.y : fq.z * fk3.z;                    \
        p3 = ((mw >> (shv + 9)) & 1u) ? p3 : 0.f;                                \
        lpart[i] += (p0 + p1) + (p2 + p3);                                       \
        __nv_bfloat162 h01 = __floats2bfloat162_rn(p0, p1);                      \
        __nv_bfloat162 h23 = __floats2bfloat162_rn(p2, p3);                      \
        __nv_bfloat162 l01 = __floats2bfloat162_rn(p0 - __bfloat162float(h01.x), \
                                                   p1 - __bfloat162float(h01.y));\
        __nv_bfloat162 l23 = __floats2bfloat162_rn(p2 - __bfloat162float(h23.x), \
                                                   p3 - __bfloat162float(h23.y));\
        pbh[BUF][sown][nt][lane] = make_uint2(bf2_bits(h01), bf2_bits(h23));     \
        pbl[BUF][sown][nt][lane] = make_uint2(bf2_bits(l01), bf2_bits(l23));     \
    }                                                                            \
} while (0)

    LOADP(0);
    CALCP(0);
    __syncthreads();

    for (int ch = 0; ch < NCH; ch++) {
        const int cur = ch & 1;
        const int chn = (ch + 1 < NCH) ? ch + 1 : ch;
        LOADP(chn);

        // A fragments for this chunk (hi/lo, both k-steps)
        size_t abase = ((((size_t)h * NCH + ch) * 2) * 8 + wid) * 32 + lane;
        uint4 a0h = __ldg(&Ahi[abase]);
        uint4 a0l = __ldg(&Alo[abase]);
        uint4 a1h = __ldg(&Ahi[abase + 256]);
        uint4 a1l = __ldg(&Alo[abase + 256]);

        // MMA phase: 3 passes per k-step, accumulator-dependency distance 16
#pragma unroll
        for (int nt = 0; nt < 16; nt++) { uint2 b = pbh[cur][0][nt][lane]; mma_bf16(acc[nt], a0h, b); }
#pragma unroll
        for (int nt = 0; nt < 16; nt++) { uint2 b = pbh[cur][0][nt][lane]; mma_bf16(acc[nt], a0l, b); }
#pragma unroll
        for (int nt = 0; nt < 16; nt++) { uint2 b = pbl[cur][0][nt][lane]; mma_bf16(acc[nt], a0h, b); }
#pragma unroll
        for (int nt = 0; nt < 16; nt++) { uint2 b = pbh[cur][1][nt][lane]; mma_bf16(acc[nt], a1h, b); }
#pragma unroll
        for (int nt = 0; nt < 16; nt++) { uint2 b = pbh[cur][1][nt][lane]; mma_bf16(acc[nt], a1l, b); }
#pragma unroll
        for (int nt = 0; nt < 16; nt++) { uint2 b = pbl[cur][1][nt][lane]; mma_bf16(acc[nt], a1h, b); }

        if (ch + 1 < NCH) CALCP(cur ^ 1);
        __syncthreads();
    }
#undef LOADP
#undef CALCP

    // -------- softmax denominators --------
#pragma unroll
    for (int i = 0; i < 4; i++) {
        float v = lpart[i];
        v += __shfl_xor_sync(0xffffffffu, v, 1);
        v += __shfl_xor_sync(0xffffffffu, v, 2);
        if (c4 == 0) atomicAdd(&lsum[(ntg * 4 + i) * 8 + r4], v);
    }
    __syncthreads();

    // -------- normalize + ELU + scatter to concat layout --------
#pragma unroll
    for (int nt = 0; nt < 16; nt++) {
        int q0 = nt * 8 + 2 * c4;
        float inv0 = 1.f / lsum[q0];
        float inv1 = 1.f / lsum[q0 + 1];
        int d0 = wid * 16 + r4;
        size_t row0 = (size_t)(qbase + q0) * (HH * DD) + h * DD;
        size_t row1 = row0 + (HH * DD);
        g_cat[row0 + d0]     = elu1(acc[nt][0] * inv0);
        g_cat[row1 + d0]     = elu1(acc[nt][1] * inv1);
        g_cat[row0 + d0 + 8] = elu1(acc[nt][2] * inv0);
        g_cat[row1 + d0 + 8] = elu1(acc[nt][3] * inv1);
    }
}

// =================================================================
// Kernel 3: x = elu(cat @ W1 + b1); out = LN(nodes + x)
// grid 512 (8 nodes/CTA), block 256 (split-k halves)
// =================================================================
__global__ void out_kernel(const float* __restrict__ nodes,
                           const float* __restrict__ W1,
                           const float* __restrict__ b1,
                           const float* __restrict__ gamma,
                           const float* __restrict__ beta,
                           float* __restrict__ out) {
    __shared__ float cs[8][1024];    // 32 KB
    __shared__ float part[8][DD];    //  4 KB
    __shared__ float rbuf[8][DD];    //  4 KB

    const int nb  = blockIdx.x * 8;
    const int tid = threadIdx.x;
    const int kh  = tid >> 7;        // which k-half
    const int col = tid & 127;

#pragma unroll
    for (int i = 0; i < 8; i++) {
        int f = tid + 256 * i;
        int r = f >> 8, c4 = f & 255;
        *(float4*)&cs[r][c4 * 4] = *(const float4*)&g_cat[(size_t)(nb + r) * 1024 + c4 * 4];
    }
    __syncthreads();

    u64 acc2[8];
#pragma unroll
    for (int n = 0; n < 8; n++) acc2[n] = 0ULL;

    const int kbeg = kh * 512;
    for (int k = kbeg; k < kbeg + 512; k += 4) {
        float w0  = __ldg(&W1[(size_t)(k + 0) * DD + col]);
        float w1v = __ldg(&W1[(size_t)(k + 1) * DD + col]);
        float w2  = __ldg(&W1[(size_t)(k + 2) * DD + col]);
        float w3  = __ldg(&W1[(size_t)(k + 3) * DD + col]);
        u64 ww01 = pack2(w0, w1v);
        u64 ww23 = pack2(w2, w3);
#pragma unroll
        for (int n = 0; n < 8; n++) {
            float4 c = *(float4*)&cs[n][k];
            acc2[n] = ffma2(pack2(c.x, c.y), ww01, acc2[n]);
            acc2[n] = ffma2(pack2(c.z, c.w), ww23, acc2[n]);
        }
    }

    float acc[8];
#pragma unroll
    for (int n = 0; n < 8; n++) {
        float2 t = unpack2(acc2[n]);
        acc[n] = t.x + t.y;
    }

    if (kh == 1) {
#pragma unroll
        for (int n = 0; n < 8; n++) part[n][col] = acc[n];
    }
    __syncthreads();
    if (kh == 0) {
        float bb = __ldg(&b1[col]);
#pragma unroll
        for (int n = 0; n < 8; n++) {
            float x = elu1(acc[n] + part[n][col] + bb);
            rbuf[n][col] = nodes[(size_t)(nb + n) * DD + col] + x;
        }
    }
    __syncthreads();

    const int w    = tid >> 5;
    const int lane = tid & 31;
    float4 G = __ldg((const float4*)&gamma[lane * 4]);
    float4 B = __ldg((const float4*)&beta[lane * 4]);
    {
        float4 r = *(float4*)&rbuf[w][lane * 4];
        float s  = r.x + r.y + r.z + r.w;
        float ss = r.x * r.x + r.y * r.y + r.z * r.z + r.w * r.w;
#pragma unroll
        for (int o = 16; o > 0; o >>= 1) {
            s  += __shfl_xor_sync(0xffffffffu, s, o);
            ss += __shfl_xor_sync(0xffffffffu, ss, o);
        }
        float mu   = s * (1.f / DD);
        float var  = ss * (1.f / DD) - mu * mu;
        float rstd = rsqrtf(var + LN_EPS);
        float4 o4;
        o4.x = (r.x - mu) * rstd * G.x + B.x;
        o4.y = (r.y - mu) * rstd * G.y + B.y;
        o4.z = (r.z - mu) * rstd * G.z + B.z;
        o4.w = (r.w - mu) * rstd * G.w + B.w;
        *(float4*)&out[(size_t)(nb + w) * DD + lane * 4] = o4;
    }
}

// =================================================================
extern "C" void kernel_launch(void* const* d_in, const int* in_sizes, int n_in,
                              void* d_out, int out_size) {
    const float* nodes = (const float*)d_in[0];
    const int*   adj   = (const int*)  d_in[1];
    const float* W     = (const float*)d_in[2];
    const float* a1    = (const float*)d_in[3];
    const float* a2    = (const float*)d_in[4];
    const float* W1    = (const float*)d_in[5];
    const float* b1    = (const float*)d_in[6];
    const float* gamma = (const float*)d_in[7];
    const float* beta  = (const float*)d_in[8];
    float* out = (float*)d_out;

    pack_kernel<<<NN * (NN / 32) / 8, 256>>>(adj);
    wh_kernel  <<<dim3(NN / 64, HH), 256>>>(nodes, W, a1, a2);
    attn_kernel<<<dim3(NN / 128, HH), 256>>>();
    out_kernel <<<NN / 8, 256>>>(nodes, W1, b1, gamma, beta, out);
}